// round 12
// baseline (speedup 1.0000x reference)
#include <cuda_runtime.h>
#include <cuda_fp16.h>

// Sinkhorn rank-one factorization: out = (s0+eps)*r_i*c_j inside the
// [nrows, ncols] block. fp16 staged copy of (s0+eps), zero-padded past
// ncols. Row-normalize + next column-sum fused (warp-per-row, column
// partials register-resident). The c-reduction runs as a fence+counter
// tail in the last-finishing block per batch: 6 launches total.

#define BB 64
#define NN 1024
#define MM 1024
#define SSPLIT 32            // row chunks (blocks per batch) for stage kernel
#define RSPLIT 16            // row chunks (blocks per batch) for fused kernel
#define PSLOTS 32            // g_part slot stride per batch
#define EPSV 1e-4f

__device__ __align__(16) __half g_sh[(size_t)BB * NN * MM];   // 128 MB (bss)
__device__ __align__(16) float  g_c[BB * MM];
__device__ __align__(16) float  g_part[(size_t)BB * PSLOTS * MM];
__device__ unsigned g_ctr[BB];                                 // zero-init bss

// swizzled smem index for column c: g = c>>3, k = c&7 -> k*128 + g
#define SWZ(c) ((((c) & 7) << 7) | ((c) >> 3))

// ---------------------------------------------------------------------------
// Tail reduction (run by ALL 256 threads of the last block of batch b):
// c[b,j] = 1/sum_{k<NS} part[b,k,j] (j<nc; else 1). Fixed order, one block
// => deterministic. atomicInc(..., NS-1) wraps to 0 => replay-safe.
// ---------------------------------------------------------------------------
template <int NS>
__device__ __forceinline__ void tail_reduce_c(int b, int nc) {
    int t = threadIdx.x;
    float4 sum = make_float4(0.f, 0.f, 0.f, 0.f);
    #pragma unroll
    for (int k = 0; k < NS; k++) {
        float4 v = ((const float4*)(g_part + ((size_t)b * PSLOTS + k) * MM))[t];
        sum.x += v.x; sum.y += v.y; sum.z += v.z; sum.w += v.w;
    }
    int col = t * 4;
    float4 o;
    o.x = (col + 0 < nc) ? 1.0f / sum.x : 1.0f;
    o.y = (col + 1 < nc) ? 1.0f / sum.y : 1.0f;
    o.z = (col + 2 < nc) ? 1.0f / sum.z : 1.0f;
    o.w = (col + 3 < nc) ? 1.0f / sum.w : 1.0f;
    ((float4*)(g_c + (size_t)b * MM))[t] = o;
}

template <int NS>
__device__ __forceinline__ void tail_gate_and_reduce(int b, int nc,
                                                     unsigned* slast) {
    __threadfence();                       // publish this block's partial
    if (threadIdx.x == 0)
        *slast = atomicInc(&g_ctr[b], NS - 1);   // wraps to 0 after last
    __syncthreads();
    if (*slast == NS - 1) {
        __threadfence();                   // order reads after the gate
        tail_reduce_c<NS>(b, nc);
    }
}

// ---------------------------------------------------------------------------
// Fused: stage (s+eps)->fp16 (zero past ncols) AND iteration-0 column-sum
// partials (implicit r = 1); last block per batch reduces c.
// ---------------------------------------------------------------------------
__global__ __launch_bounds__(256) void stage_colsum0(
        const float* __restrict__ s,
        const int* __restrict__ nrows,
        const int* __restrict__ ncols) {
    __shared__ unsigned slast;
    int b = blockIdx.y;
    int t = threadIdx.x;
    int nr = nrows[b], nc = ncols[b];
    int chunk = (nr + SSPLIT - 1) / SSPLIT;
    int i0 = blockIdx.x * chunk;
    int i1 = min(i0 + chunk, nr);
    int j = t * 4;
    bool m0 = j < nc, m1 = j + 1 < nc, m2 = j + 2 < nc, m3 = j + 3 < nc;

    float4 acc = make_float4(0.f, 0.f, 0.f, 0.f);
    const float4* __restrict__ sp =
        (const float4*)(s + ((size_t)b * NN + i0) * MM) + t;
    __half2* __restrict__ hp =
        (__half2*)(g_sh + ((size_t)b * NN + i0) * MM) + t * 2;

    for (int i = i0; i < i1; i++) {
        float x0 = 0.f, x1 = 0.f, x2 = 0.f, x3 = 0.f;
        if (m0) {
            float4 v = *sp;
            x0 = v.x + EPSV;
            x1 = m1 ? v.y + EPSV : 0.f;
            x2 = m2 ? v.z + EPSV : 0.f;
            x3 = m3 ? v.w + EPSV : 0.f;
        }
        hp[0] = __floats2half2_rn(x0, x1);
        hp[1] = __floats2half2_rn(x2, x3);
        acc.x += x0; acc.y += x1; acc.z += x2; acc.w += x3;
        sp += MM / 4;
        hp += MM / 2;
    }
    ((float4*)(g_part + ((size_t)b * PSLOTS + blockIdx.x) * MM))[t] = acc;

    tail_gate_and_reduce<SSPLIT>(b, nc, &slast);
}

// ---------------------------------------------------------------------------
// FUSED row-normalize + next column-sum (R11-proven body) + tail c-reduce.
// ---------------------------------------------------------------------------
__global__ __launch_bounds__(256) void rowcol_fused(
        const int* __restrict__ nrows,
        const int* __restrict__ ncols) {
    __shared__ float c_s[MM];            // swizzled
    __shared__ float sacc[8][MM];        // swizzled, per-warp
    __shared__ unsigned slast;
    int b = blockIdx.y;
    int t = threadIdx.x;
    int lane = t & 31, w = t >> 5;
    int nr = nrows[b], nc = ncols[b];
    int chunk = (nr + RSPLIT - 1) / RSPLIT;
    int i0 = blockIdx.x * chunk;
    int i1 = min(i0 + chunk, nr);

    {   // stage c into swizzled smem (once per block)
        float4 cv = ((const float4*)(g_c + (size_t)b * MM))[t];
        int col = t * 4;
        c_s[SWZ(col + 0)] = cv.x;
        c_s[SWZ(col + 1)] = cv.y;
        c_s[SWZ(col + 2)] = cv.z;
        c_s[SWZ(col + 3)] = cv.w;
    }
    float colacc[32];
    #pragma unroll
    for (int k = 0; k < 32; k++) colacc[k] = 0.f;
    __syncthreads();

    const uint4* __restrict__ hb = (const uint4*)(g_sh + (size_t)b * NN * MM);
    for (int i = i0 + w; i < i1; i += 8) {
        const uint4* hp = hb + (size_t)i * (MM / 8);
        uint4 raw[4];
        #pragma unroll
        for (int q = 0; q < 4; q++) raw[q] = hp[lane + 32 * q];

        float dot = 0.f;
        #pragma unroll
        for (int q = 0; q < 4; q++) {
            int g = lane + 32 * q;
            float2 a0 = __half22float2(*(__half2*)&raw[q].x);
            float2 a1 = __half22float2(*(__half2*)&raw[q].y);
            float2 a2 = __half22float2(*(__half2*)&raw[q].z);
            float2 a3 = __half22float2(*(__half2*)&raw[q].w);
            dot += a0.x * c_s[0 * 128 + g] + a0.y * c_s[1 * 128 + g]
                 + a1.x * c_s[2 * 128 + g] + a1.y * c_s[3 * 128 + g]
                 + a2.x * c_s[4 * 128 + g] + a2.y * c_s[5 * 128 + g]
                 + a3.x * c_s[6 * 128 + g] + a3.y * c_s[7 * 128 + g];
        }
        #pragma unroll
        for (int o = 16; o; o >>= 1)
            dot += __shfl_xor_sync(0xffffffffu, dot, o);
        float r = 1.0f / dot;

        #pragma unroll
        for (int q = 0; q < 4; q++) {
            float2 a0 = __half22float2(*(__half2*)&raw[q].x);
            float2 a1 = __half22float2(*(__half2*)&raw[q].y);
            float2 a2 = __half22float2(*(__half2*)&raw[q].z);
            float2 a3 = __half22float2(*(__half2*)&raw[q].w);
            colacc[q * 8 + 0] += r * a0.x;
            colacc[q * 8 + 1] += r * a0.y;
            colacc[q * 8 + 2] += r * a1.x;
            colacc[q * 8 + 3] += r * a1.y;
            colacc[q * 8 + 4] += r * a2.x;
            colacc[q * 8 + 5] += r * a2.y;
            colacc[q * 8 + 6] += r * a3.x;
            colacc[q * 8 + 7] += r * a3.y;
        }
    }

    // spill warp partials (conflict-free swizzled addresses)
    #pragma unroll
    for (int q = 0; q < 4; q++) {
        int g = lane + 32 * q;
        #pragma unroll
        for (int k = 0; k < 8; k++)
            sacc[w][k * 128 + g] = colacc[q * 8 + k];
    }
    __syncthreads();

    // block reduce: thread t -> columns 4t..4t+3, one float4 partial write
    int col = t * 4;
    float4 o;
    float* po = &o.x;
    #pragma unroll
    for (int m = 0; m < 4; m++) {
        int idx = SWZ(col + m);
        float sm = 0.f;
        #pragma unroll
        for (int ww = 0; ww < 8; ww++) sm += sacc[ww][idx];
        po[m] = sm;
    }
    ((float4*)(g_part + ((size_t)b * PSLOTS + blockIdx.x) * MM))[t] = o;

    tail_gate_and_reduce<RSPLIT>(b, nc, &slast);
}

// ---------------------------------------------------------------------------
// Fused iter-9 rowsum + output, fp16 source (R10-proven). Warp per row.
// ---------------------------------------------------------------------------
__global__ __launch_bounds__(256) void rowsum_final_h(
        const int* __restrict__ nrows,
        const int* __restrict__ ncols,
        float* __restrict__ out) {
    int b = blockIdx.y;
    int lane = threadIdx.x & 31, w = threadIdx.x >> 5;
    int i = blockIdx.x * 8 + w;
    int nr = nrows[b], nc = ncols[b];
    float4* __restrict__ op = (float4*)(out + ((size_t)b * NN + i) * MM);

    if (i >= nr) {
        float4 z = make_float4(0.f, 0.f, 0.f, 0.f);
        #pragma unroll
        for (int k = lane; k < MM / 4; k += 32) op[k] = z;
        return;
    }

    const uint4* __restrict__ hp =
        (const uint4*)(g_sh + ((size_t)b * NN + i) * MM);
    const float4* __restrict__ cp = (const float4*)(g_c + (size_t)b * MM);
    int ng8 = (nc + 7) >> 3;

    uint4 hreg[4];
    float acc = 0.f;
    #pragma unroll
    for (int q = 0; q < 4; q++) {
        int g = lane + 32 * q;
        uint4 raw = make_uint4(0u, 0u, 0u, 0u);
        if (g < ng8) raw = hp[g];
        hreg[q] = raw;
        float4 c0 = cp[2 * g], c1 = cp[2 * g + 1];
        float2 a0 = __half22float2(*(__half2*)&raw.x);
        float2 a1 = __half22float2(*(__half2*)&raw.y);
        float2 a2 = __half22float2(*(__half2*)&raw.z);
        float2 a3 = __half22float2(*(__half2*)&raw.w);
        acc += a0.x * c0.x + a0.y * c0.y + a1.x * c0.z + a1.y * c0.w
             + a2.x * c1.x + a2.y * c1.y + a3.x * c1.z + a3.y * c1.w;
    }
    #pragma unroll
    for (int o = 16; o; o >>= 1) acc += __shfl_xor_sync(0xffffffffu, acc, o);
    float r = 1.0f / acc;

    #pragma unroll
    for (int q = 0; q < 4; q++) {
        int g = lane + 32 * q;
        uint4 raw = hreg[q];
        float4 c0 = cp[2 * g], c1 = cp[2 * g + 1];
        float2 a0 = __half22float2(*(__half2*)&raw.x);
        float2 a1 = __half22float2(*(__half2*)&raw.y);
        float2 a2 = __half22float2(*(__half2*)&raw.z);
        float2 a3 = __half22float2(*(__half2*)&raw.w);
        float4 o0, o1;
        o0.x = a0.x * r * c0.x;  o0.y = a0.y * r * c0.y;
        o0.z = a1.x * r * c0.z;  o0.w = a1.y * r * c0.w;
        o1.x = a2.x * r * c1.x;  o1.y = a2.y * r * c1.y;
        o1.z = a3.x * r * c1.z;  o1.w = a3.y * r * c1.w;
        op[2 * g] = o0;
        op[2 * g + 1] = o1;
    }
}

// ---------------------------------------------------------------------------
extern "C" void kernel_launch(void* const* d_in, const int* in_sizes, int n_in,
                              void* d_out, int out_size) {
    const float* s     = (const float*)d_in[0];
    const int*   nrows = (const int*)d_in[1];
    const int*   ncols = (const int*)d_in[2];
    float*       out   = (float*)d_out;

    dim3 stGrid(SSPLIT, BB),   blk(256);
    dim3 fuGrid(RSPLIT, BB);
    dim3 rsGrid(NN / 8, BB);

    // iter 0 (col): stage + colsum + tail c-reduce
    stage_colsum0<<<stGrid, blk>>>(s, nrows, ncols);

    // iters 1..8: four fused (row-normalize + next column-sum + tail reduce)
    for (int p = 0; p < 4; ++p)
        rowcol_fused<<<fuGrid, blk>>>(nrows, ncols);

    // iter 9 (row) fused with output materialization, fp16 source
    rowsum_final_h<<<rsGrid, blk>>>(nrows, ncols, out);
}

// round 14
// speedup vs baseline: 1.0938x; 1.0938x over previous
#include <cuda_runtime.h>
#include <cuda_fp16.h>

// Sinkhorn rank-one factorization: out = (s0+eps)*r_i*c_j inside the
// [nrows, ncols] block. fp16 staged copy of (s0+eps), zero-padded past
// ncols. Row-normalize + next column-sum fused (warp-per-row, pipelined
// loads, column partials register-resident). Each fused block computes c
// itself from the previous pass's partials (ping-pong buffers A/B), so
// only ONE standalone c-reduction remains (before the output kernel).

#define BB 64
#define NN 1024
#define MM 1024
#define SSPLIT 32            // blocks per batch, stage kernel (slots in A)
#define RSPLIT 16            // blocks per batch, fused kernel (slots in B)
#define EPSV 1e-4f

__device__ __align__(16) __half g_sh[(size_t)BB * NN * MM];   // 128 MB (bss)
__device__ __align__(16) float  g_c[BB * MM];
__device__ __align__(16) float  g_pA[(size_t)BB * SSPLIT * MM];  // 8 MB
__device__ __align__(16) float  g_pB[(size_t)BB * RSPLIT * MM];  // 4 MB

// swizzled smem index for column c: g = c>>3, k = c&7 -> k*128 + g
#define SWZ(c) ((((c) & 7) << 7) | ((c) >> 3))

// ---------------------------------------------------------------------------
// Stage (s+eps)->fp16 (zero past ncols) AND iteration-0 column-sum partials
// (implicit r = 1) into buffer A. R11-proven body.
// ---------------------------------------------------------------------------
__global__ __launch_bounds__(256) void stage_colsum0(
        const float* __restrict__ s,
        const int* __restrict__ nrows,
        const int* __restrict__ ncols) {
    int b = blockIdx.y;
    int t = threadIdx.x;
    int nr = nrows[b], nc = ncols[b];
    int chunk = (nr + SSPLIT - 1) / SSPLIT;
    int i0 = blockIdx.x * chunk;
    int i1 = min(i0 + chunk, nr);
    int j = t * 4;
    bool m0 = j < nc, m1 = j + 1 < nc, m2 = j + 2 < nc, m3 = j + 3 < nc;

    float4 acc = make_float4(0.f, 0.f, 0.f, 0.f);
    const float4* __restrict__ sp =
        (const float4*)(s + ((size_t)b * NN + i0) * MM) + t;
    __half2* __restrict__ hp =
        (__half2*)(g_sh + ((size_t)b * NN + i0) * MM) + t * 2;

    for (int i = i0; i < i1; i++) {
        float x0 = 0.f, x1 = 0.f, x2 = 0.f, x3 = 0.f;
        if (m0) {
            float4 v = *sp;
            x0 = v.x + EPSV;
            x1 = m1 ? v.y + EPSV : 0.f;
            x2 = m2 ? v.z + EPSV : 0.f;
            x3 = m3 ? v.w + EPSV : 0.f;
        }
        hp[0] = __floats2half2_rn(x0, x1);
        hp[1] = __floats2half2_rn(x2, x3);
        acc.x += x0; acc.y += x1; acc.z += x2; acc.w += x3;
        sp += MM / 4;
        hp += MM / 2;
    }
    ((float4*)(g_pA + ((size_t)b * SSPLIT + blockIdx.x) * MM))[t] = acc;
}

// ---------------------------------------------------------------------------
// FUSED pass: prologue reduces the previous pass's NS_IN partial slots into
// c (swizzled smem, identical deterministic result in every block), then
// row-normalize + next column-sum with a 2-deep load pipeline per warp.
// AB=true: in = A (stride SSPLIT), out = B. AB=false: in = B, out = A.
// ---------------------------------------------------------------------------
template <int NS_IN, bool AB>
__global__ __launch_bounds__(256, 2) void rowcol_fused(
        const int* __restrict__ nrows,
        const int* __restrict__ ncols) {
    __shared__ float c_s[MM];            // swizzled
    __shared__ float sacc[8][MM];        // swizzled, per-warp
    int b = blockIdx.y;
    int t = threadIdx.x;
    int lane = t & 31, w = t >> 5;
    int nr = nrows[b], nc = ncols[b];
    int chunk = (nr + RSPLIT - 1) / RSPLIT;
    int i0 = blockIdx.x * chunk;
    int i1 = min(i0 + chunk, nr);

    const float* __restrict__ pin  = AB ? g_pA : g_pB;
    float*       __restrict__ pout = AB ? g_pB : g_pA;
    const int PS_IN  = AB ? SSPLIT : RSPLIT;
    const int PS_OUT = AB ? RSPLIT : SSPLIT;

    {   // prologue: c[col] = 1/sum_k part_in[b,k,col]  (col<nc; else 1)
        float4 sum = make_float4(0.f, 0.f, 0.f, 0.f);
        #pragma unroll
        for (int k = 0; k < NS_IN; k++) {
            float4 v = ((const float4*)(pin + ((size_t)b * PS_IN + k) * MM))[t];
            sum.x += v.x; sum.y += v.y; sum.z += v.z; sum.w += v.w;
        }
        int col = t * 4;
        c_s[SWZ(col + 0)] = (col + 0 < nc) ? 1.0f / sum.x : 1.0f;
        c_s[SWZ(col + 1)] = (col + 1 < nc) ? 1.0f / sum.y : 1.0f;
        c_s[SWZ(col + 2)] = (col + 2 < nc) ? 1.0f / sum.z : 1.0f;
        c_s[SWZ(col + 3)] = (col + 3 < nc) ? 1.0f / sum.w : 1.0f;
    }
    float colacc[32];
    #pragma unroll
    for (int k = 0; k < 32; k++) colacc[k] = 0.f;
    __syncthreads();

    const uint4* __restrict__ hb = (const uint4*)(g_sh + (size_t)b * NN * MM);
    int i = i0 + w;
    uint4 raw[4];
    if (i < i1) {
        const uint4* hp = hb + (size_t)i * (MM / 8);
        #pragma unroll
        for (int q = 0; q < 4; q++) raw[q] = hp[lane + 32 * q];
    }
    for (; i < i1; i += 8) {
        // prefetch next row before the dependent reduction of this row
        uint4 rawN[4];
        int inx = i + 8;
        if (inx < i1) {
            const uint4* hp = hb + (size_t)inx * (MM / 8);
            #pragma unroll
            for (int q = 0; q < 4; q++) rawN[q] = hp[lane + 32 * q];
        }

        float dot = 0.f;
        #pragma unroll
        for (int q = 0; q < 4; q++) {
            int g = lane + 32 * q;
            float2 a0 = __half22float2(*(__half2*)&raw[q].x);
            float2 a1 = __half22float2(*(__half2*)&raw[q].y);
            float2 a2 = __half22float2(*(__half2*)&raw[q].z);
            float2 a3 = __half22float2(*(__half2*)&raw[q].w);
            dot += a0.x * c_s[0 * 128 + g] + a0.y * c_s[1 * 128 + g]
                 + a1.x * c_s[2 * 128 + g] + a1.y * c_s[3 * 128 + g]
                 + a2.x * c_s[4 * 128 + g] + a2.y * c_s[5 * 128 + g]
                 + a3.x * c_s[6 * 128 + g] + a3.y * c_s[7 * 128 + g];
        }
        #pragma unroll
        for (int o = 16; o; o >>= 1)
            dot += __shfl_xor_sync(0xffffffffu, dot, o);
        float r = 1.0f / dot;

        #pragma unroll
        for (int q = 0; q < 4; q++) {
            float2 a0 = __half22float2(*(__half2*)&raw[q].x);
            float2 a1 = __half22float2(*(__half2*)&raw[q].y);
            float2 a2 = __half22float2(*(__half2*)&raw[q].z);
            float2 a3 = __half22float2(*(__half2*)&raw[q].w);
            colacc[q * 8 + 0] += r * a0.x;
            colacc[q * 8 + 1] += r * a0.y;
            colacc[q * 8 + 2] += r * a1.x;
            colacc[q * 8 + 3] += r * a1.y;
            colacc[q * 8 + 4] += r * a2.x;
            colacc[q * 8 + 5] += r * a2.y;
            colacc[q * 8 + 6] += r * a3.x;
            colacc[q * 8 + 7] += r * a3.y;
        }
        #pragma unroll
        for (int q = 0; q < 4; q++) raw[q] = rawN[q];
    }

    // spill warp partials (conflict-free swizzled addresses)
    #pragma unroll
    for (int q = 0; q < 4; q++) {
        int g = lane + 32 * q;
        #pragma unroll
        for (int k = 0; k < 8; k++)
            sacc[w][k * 128 + g] = colacc[q * 8 + k];
    }
    __syncthreads();

    // block reduce: thread t -> columns 4t..4t+3, one float4 partial write
    int col = t * 4;
    float4 o;
    float* po = &o.x;
    #pragma unroll
    for (int m = 0; m < 4; m++) {
        int idx = SWZ(col + m);
        float sm = 0.f;
        #pragma unroll
        for (int ww = 0; ww < 8; ww++) sm += sacc[ww][idx];
        po[m] = sm;
    }
    ((float4*)(pout + ((size_t)b * PS_OUT + blockIdx.x) * MM))[t] = o;
}

// ---------------------------------------------------------------------------
// Final c-reduction (before output): c = 1/sum of the RSPLIT slots in A.
// ---------------------------------------------------------------------------
__global__ __launch_bounds__(256) void reduce_c_final(
        const int* __restrict__ ncols) {
    int b = blockIdx.y;
    int j = blockIdx.x * 256 + threadIdx.x;
    float sum = 0.f;
    #pragma unroll
    for (int k = 0; k < RSPLIT; k++)
        sum += g_pA[((size_t)b * SSPLIT + k) * MM + j];
    g_c[b * MM + j] = (j < ncols[b]) ? (1.0f / sum) : 1.0f;
}

// ---------------------------------------------------------------------------
// Fused iter-9 rowsum + output, fp16 source (R10-proven). Warp per row.
// ---------------------------------------------------------------------------
__global__ __launch_bounds__(256) void rowsum_final_h(
        const int* __restrict__ nrows,
        const int* __restrict__ ncols,
        float* __restrict__ out) {
    int b = blockIdx.y;
    int lane = threadIdx.x & 31, w = threadIdx.x >> 5;
    int i = blockIdx.x * 8 + w;
    int nr = nrows[b], nc = ncols[b];
    float4* __restrict__ op = (float4*)(out + ((size_t)b * NN + i) * MM);

    if (i >= nr) {
        float4 z = make_float4(0.f, 0.f, 0.f, 0.f);
        #pragma unroll
        for (int k = lane; k < MM / 4; k += 32) op[k] = z;
        return;
    }

    const uint4* __restrict__ hp =
        (const uint4*)(g_sh + ((size_t)b * NN + i) * MM);
    const float4* __restrict__ cp = (const float4*)(g_c + (size_t)b * MM);
    int ng8 = (nc + 7) >> 3;

    uint4 hreg[4];
    float acc = 0.f;
    #pragma unroll
    for (int q = 0; q < 4; q++) {
        int g = lane + 32 * q;
        uint4 raw = make_uint4(0u, 0u, 0u, 0u);
        if (g < ng8) raw = hp[g];
        hreg[q] = raw;
        float4 c0 = cp[2 * g], c1 = cp[2 * g + 1];
        float2 a0 = __half22float2(*(__half2*)&raw.x);
        float2 a1 = __half22float2(*(__half2*)&raw.y);
        float2 a2 = __half22float2(*(__half2*)&raw.z);
        float2 a3 = __half22float2(*(__half2*)&raw.w);
        acc += a0.x * c0.x + a0.y * c0.y + a1.x * c0.z + a1.y * c0.w
             + a2.x * c1.x + a2.y * c1.y + a3.x * c1.z + a3.y * c1.w;
    }
    #pragma unroll
    for (int o = 16; o; o >>= 1) acc += __shfl_xor_sync(0xffffffffu, acc, o);
    float r = 1.0f / acc;

    #pragma unroll
    for (int q = 0; q < 4; q++) {
        int g = lane + 32 * q;
        uint4 raw = hreg[q];
        float4 c0 = cp[2 * g], c1 = cp[2 * g + 1];
        float2 a0 = __half22float2(*(__half2*)&raw.x);
        float2 a1 = __half22float2(*(__half2*)&raw.y);
        float2 a2 = __half22float2(*(__half2*)&raw.z);
        float2 a3 = __half22float2(*(__half2*)&raw.w);
        float4 o0, o1;
        o0.x = a0.x * r * c0.x;  o0.y = a0.y * r * c0.y;
        o0.z = a1.x * r * c0.z;  o0.w = a1.y * r * c0.w;
        o1.x = a2.x * r * c1.x;  o1.y = a2.y * r * c1.y;
        o1.z = a3.x * r * c1.z;  o1.w = a3.y * r * c1.w;
        op[2 * g] = o0;
        op[2 * g + 1] = o1;
    }
}

// ---------------------------------------------------------------------------
extern "C" void kernel_launch(void* const* d_in, const int* in_sizes, int n_in,
                              void* d_out, int out_size) {
    const float* s     = (const float*)d_in[0];
    const int*   nrows = (const int*)d_in[1];
    const int*   ncols = (const int*)d_in[2];
    float*       out   = (float*)d_out;

    dim3 stGrid(SSPLIT, BB),   blk(256);
    dim3 fuGrid(RSPLIT, BB);
    dim3 rcGrid(MM / 256, BB);
    dim3 rsGrid(NN / 8, BB);

    // iter 0 (col): stage + colsum (r = 1) -> partials in A
    stage_colsum0<<<stGrid, blk>>>(s, nrows, ncols);

    // iters 1..8: fused (c-from-partials prologue + row-norm + next colsum)
    rowcol_fused<SSPLIT, true ><<<fuGrid, blk>>>(nrows, ncols);  // A -> B
    rowcol_fused<RSPLIT, false><<<fuGrid, blk>>>(nrows, ncols);  // B -> A
    rowcol_fused<RSPLIT, true ><<<fuGrid, blk>>>(nrows, ncols);  // A -> B
    rowcol_fused<RSPLIT, false><<<fuGrid, blk>>>(nrows, ncols);  // B -> A

    // final c from A, then iter 9 (row) fused with output materialization
    reduce_c_final<<<rcGrid, blk>>>(ncols);
    rowsum_final_h<<<rsGrid, blk>>>(nrows, ncols, out);
}

// round 15
// speedup vs baseline: 1.1088x; 1.0137x over previous
#include <cuda_runtime.h>
#include <cuda_fp16.h>

// Sinkhorn rank-one factorization: out = (s0+eps)*r_i*c_j inside the
// [nrows, ncols] block. fp16 staged copy of (s0+eps) stored COMPACTED:
// per-batch row stride sb = align(ncols,64) elements, nrows rows only,
// base offsets via device-side prefix sum. Working set ~74 MB < L2
// (126 MB) => fused matvec passes run mostly from L2.
// Padding cols [ncols, sb) are stored as zero => no masking in hot loops.

#define BB 64
#define NN 1024
#define MM 1024
#define SSPLIT 32            // blocks per batch, stage kernel (slots in A)
#define RSPLIT 16            // blocks per batch, fused kernel (slots in B)
#define EPSV 1e-4f

__device__ __align__(16) __half g_sh[(size_t)BB * NN * MM];   // cap (bss)
__device__ __align__(16) float  g_c[BB * MM];
__device__ __align__(16) float  g_pA[(size_t)BB * SSPLIT * MM];  // 8 MB
__device__ __align__(16) float  g_pB[(size_t)BB * RSPLIT * MM];  // 4 MB
__device__ unsigned long long g_off[BB];   // element offset of batch base
__device__ int               g_strd[BB];   // row stride (elements, mult 64)

// swizzled smem index for column c: g = c>>3, k = c&7 -> k*128 + g
#define SWZ(c) ((((c) & 7) << 7) | ((c) >> 3))

// ---------------------------------------------------------------------------
// Offsets: serial prefix over 64 batches (single thread; trivial).
// ---------------------------------------------------------------------------
__global__ void compute_offsets(const int* __restrict__ nrows,
                                const int* __restrict__ ncols) {
    if (threadIdx.x == 0 && blockIdx.x == 0) {
        unsigned long long off = 0;
        for (int b = 0; b < BB; b++) {
            int sb = (ncols[b] + 63) & ~63;
            g_off[b] = off;
            g_strd[b] = sb;
            off += (unsigned long long)nrows[b] * (unsigned long long)sb;
        }
    }
}

// ---------------------------------------------------------------------------
// Stage (s+eps)->fp16 compacted (zero-fill [nc, sb)) AND iteration-0
// column-sum partials (implicit r = 1) into buffer A.
// ---------------------------------------------------------------------------
__global__ __launch_bounds__(256) void stage_colsum0(
        const float* __restrict__ s,
        const int* __restrict__ nrows,
        const int* __restrict__ ncols) {
    int b = blockIdx.y;
    int t = threadIdx.x;
    int nr = nrows[b], nc = ncols[b];
    int sb = g_strd[b];
    unsigned long long off = g_off[b];
    int chunk = (nr + SSPLIT - 1) / SSPLIT;
    int i0 = blockIdx.x * chunk;
    int i1 = min(i0 + chunk, nr);
    int j = t * 4;
    bool inb = j < sb;                       // this thread has a staged slot
    bool m0 = j < nc, m1 = j + 1 < nc, m2 = j + 2 < nc, m3 = j + 3 < nc;

    float4 acc = make_float4(0.f, 0.f, 0.f, 0.f);
    const float4* __restrict__ sp =
        (const float4*)(s + ((size_t)b * NN + i0) * MM) + t;
    __half2* __restrict__ hp =
        (__half2*)(g_sh + off + (size_t)i0 * sb) + t * 2;

    for (int i = i0; i < i1; i++) {
        if (inb) {
            float x0 = 0.f, x1 = 0.f, x2 = 0.f, x3 = 0.f;
            if (m0) {
                float4 v = *sp;
                x0 = v.x + EPSV;
                x1 = m1 ? v.y + EPSV : 0.f;
                x2 = m2 ? v.z + EPSV : 0.f;
                x3 = m3 ? v.w + EPSV : 0.f;
            }
            hp[0] = __floats2half2_rn(x0, x1);
            hp[1] = __floats2half2_rn(x2, x3);
            acc.x += x0; acc.y += x1; acc.z += x2; acc.w += x3;
        }
        sp += MM / 4;
        hp += sb / 2;
    }
    ((float4*)(g_pA + ((size_t)b * SSPLIT + blockIdx.x) * MM))[t] = acc;
}

// ---------------------------------------------------------------------------
// FUSED pass: prologue reduces previous pass's NS_IN partial slots into c
// (swizzled smem; identical deterministic result in every block), then
// row-normalize + next column-sum, 2-deep load pipeline, compacted rows.
// AB=true: in = A (stride SSPLIT), out = B. AB=false: in = B, out = A.
// ---------------------------------------------------------------------------
template <int NS_IN, bool AB>
__global__ __launch_bounds__(256, 2) void rowcol_fused(
        const int* __restrict__ nrows,
        const int* __restrict__ ncols) {
    __shared__ float c_s[MM];            // swizzled
    __shared__ float sacc[8][MM];        // swizzled, per-warp
    int b = blockIdx.y;
    int t = threadIdx.x;
    int lane = t & 31, w = t >> 5;
    int nr = nrows[b], nc = ncols[b];
    int sb = g_strd[b];
    int sbg = sb >> 3;                   // granules per row (<=128)
    unsigned long long off = g_off[b];
    int chunk = (nr + RSPLIT - 1) / RSPLIT;
    int i0 = blockIdx.x * chunk;
    int i1 = min(i0 + chunk, nr);

    const float* __restrict__ pin  = AB ? g_pA : g_pB;
    float*       __restrict__ pout = AB ? g_pB : g_pA;
    const int PS_IN  = AB ? SSPLIT : RSPLIT;
    const int PS_OUT = AB ? RSPLIT : SSPLIT;

    {   // prologue: c[col] = 1/sum_k part_in[b,k,col]  (col<nc; else 1)
        float4 sum = make_float4(0.f, 0.f, 0.f, 0.f);
        #pragma unroll
        for (int k = 0; k < NS_IN; k++) {
            float4 v = ((const float4*)(pin + ((size_t)b * PS_IN + k) * MM))[t];
            sum.x += v.x; sum.y += v.y; sum.z += v.z; sum.w += v.w;
        }
        int col = t * 4;
        c_s[SWZ(col + 0)] = (col + 0 < nc) ? 1.0f / sum.x : 1.0f;
        c_s[SWZ(col + 1)] = (col + 1 < nc) ? 1.0f / sum.y : 1.0f;
        c_s[SWZ(col + 2)] = (col + 2 < nc) ? 1.0f / sum.z : 1.0f;
        c_s[SWZ(col + 3)] = (col + 3 < nc) ? 1.0f / sum.w : 1.0f;
    }
    float colacc[32];
    #pragma unroll
    for (int k = 0; k < 32; k++) colacc[k] = 0.f;
    __syncthreads();

    bool msk[4];
    #pragma unroll
    for (int q = 0; q < 4; q++) msk[q] = (lane + 32 * q) < sbg;

    const uint4* __restrict__ hb = (const uint4*)(g_sh + off);
    const uint4 Z = make_uint4(0u, 0u, 0u, 0u);
    int i = i0 + w;
    uint4 raw[4];
    if (i < i1) {
        const uint4* hp = hb + (size_t)i * sbg;
        #pragma unroll
        for (int q = 0; q < 4; q++) raw[q] = msk[q] ? hp[lane + 32 * q] : Z;
    }
    for (; i < i1; i += 8) {
        // prefetch next row before the dependent reduction of this row
        uint4 rawN[4];
        int inx = i + 8;
        if (inx < i1) {
            const uint4* hp = hb + (size_t)inx * sbg;
            #pragma unroll
            for (int q = 0; q < 4; q++) rawN[q] = msk[q] ? hp[lane + 32 * q] : Z;
        }

        float dot = 0.f;
        #pragma unroll
        for (int q = 0; q < 4; q++) {
            int g = lane + 32 * q;
            float2 a0 = __half22float2(*(__half2*)&raw[q].x);
            float2 a1 = __half22float2(*(__half2*)&raw[q].y);
            float2 a2 = __half22float2(*(__half2*)&raw[q].z);
            float2 a3 = __half22float2(*(__half2*)&raw[q].w);
            dot += a0.x * c_s[0 * 128 + g] + a0.y * c_s[1 * 128 + g]
                 + a1.x * c_s[2 * 128 + g] + a1.y * c_s[3 * 128 + g]
                 + a2.x * c_s[4 * 128 + g] + a2.y * c_s[5 * 128 + g]
                 + a3.x * c_s[6 * 128 + g] + a3.y * c_s[7 * 128 + g];
        }
        #pragma unroll
        for (int o = 16; o; o >>= 1)
            dot += __shfl_xor_sync(0xffffffffu, dot, o);
        float r = 1.0f / dot;

        #pragma unroll
        for (int q = 0; q < 4; q++) {
            float2 a0 = __half22float2(*(__half2*)&raw[q].x);
            float2 a1 = __half22float2(*(__half2*)&raw[q].y);
            float2 a2 = __half22float2(*(__half2*)&raw[q].z);
            float2 a3 = __half22float2(*(__half2*)&raw[q].w);
            colacc[q * 8 + 0] += r * a0.x;
            colacc[q * 8 + 1] += r * a0.y;
            colacc[q * 8 + 2] += r * a1.x;
            colacc[q * 8 + 3] += r * a1.y;
            colacc[q * 8 + 4] += r * a2.x;
            colacc[q * 8 + 5] += r * a2.y;
            colacc[q * 8 + 6] += r * a3.x;
            colacc[q * 8 + 7] += r * a3.y;
        }
        #pragma unroll
        for (int q = 0; q < 4; q++) raw[q] = rawN[q];
    }

    // spill warp partials (conflict-free swizzled addresses)
    #pragma unroll
    for (int q = 0; q < 4; q++) {
        int g = lane + 32 * q;
        #pragma unroll
        for (int k = 0; k < 8; k++)
            sacc[w][k * 128 + g] = colacc[q * 8 + k];
    }
    __syncthreads();

    // block reduce: thread t -> columns 4t..4t+3, one float4 partial write
    int col = t * 4;
    float4 o;
    float* po = &o.x;
    #pragma unroll
    for (int m = 0; m < 4; m++) {
        int idx = SWZ(col + m);
        float sm = 0.f;
        #pragma unroll
        for (int ww = 0; ww < 8; ww++) sm += sacc[ww][idx];
        po[m] = sm;
    }
    ((float4*)(pout + ((size_t)b * PS_OUT + blockIdx.x) * MM))[t] = o;
}

// ---------------------------------------------------------------------------
// Final c-reduction (before output): c = 1/sum of the RSPLIT slots in A.
// ---------------------------------------------------------------------------
__global__ __launch_bounds__(256) void reduce_c_final(
        const int* __restrict__ ncols) {
    int b = blockIdx.y;
    int j = blockIdx.x * 256 + threadIdx.x;
    float sum = 0.f;
    #pragma unroll
    for (int k = 0; k < RSPLIT; k++)
        sum += g_pA[((size_t)b * SSPLIT + k) * MM + j];
    g_c[b * MM + j] = (j < ncols[b]) ? (1.0f / sum) : 1.0f;
}

// ---------------------------------------------------------------------------
// Fused iter-9 rowsum + output, compacted fp16 source. Warp per row.
// Staged padding is zero => cols in [nc, sb) output 0; granules >= sbg
// write explicit zeros; rows >= nr write zeros without reads.
// ---------------------------------------------------------------------------
__global__ __launch_bounds__(256) void rowsum_final_h(
        const int* __restrict__ nrows,
        const int* __restrict__ ncols,
        float* __restrict__ out) {
    int b = blockIdx.y;
    int lane = threadIdx.x & 31, w = threadIdx.x >> 5;
    int i = blockIdx.x * 8 + w;
    int nr = nrows[b];
    int sbg = g_strd[b] >> 3;
    float4* __restrict__ op = (float4*)(out + ((size_t)b * NN + i) * MM);

    if (i >= nr) {
        float4 z = make_float4(0.f, 0.f, 0.f, 0.f);
        #pragma unroll
        for (int k = lane; k < MM / 4; k += 32) op[k] = z;
        return;
    }

    const uint4* __restrict__ hp =
        (const uint4*)(g_sh + g_off[b]) + (size_t)i * sbg;
    const float4* __restrict__ cp = (const float4*)(g_c + (size_t)b * MM);

    uint4 hreg[4];
    float acc = 0.f;
    #pragma unroll
    for (int q = 0; q < 4; q++) {
        int g = lane + 32 * q;
        uint4 raw = make_uint4(0u, 0u, 0u, 0u);
        if (g < sbg) raw = hp[g];
        hreg[q] = raw;
        float4 c0 = cp[2 * g], c1 = cp[2 * g + 1];
        float2 a0 = __half22float2(*(__half2*)&raw.x);
        float2 a1 = __half22float2(*(__half2*)&raw.y);
        float2 a2 = __half22float2(*(__half2*)&raw.z);
        float2 a3 = __half22float2(*(__half2*)&raw.w);
        acc += a0.x * c0.x + a0.y * c0.y + a1.x * c0.z + a1.y * c0.w
             + a2.x * c1.x + a2.y * c1.y + a3.x * c1.z + a3.y * c1.w;
    }
    #pragma unroll
    for (int o = 16; o; o >>= 1) acc += __shfl_xor_sync(0xffffffffu, acc, o);
    float r = 1.0f / acc;

    #pragma unroll
    for (int q = 0; q < 4; q++) {
        int g = lane + 32 * q;
        uint4 raw = hreg[q];
        float4 c0 = cp[2 * g], c1 = cp[2 * g + 1];
        float2 a0 = __half22float2(*(__half2*)&raw.x);
        float2 a1 = __half22float2(*(__half2*)&raw.y);
        float2 a2 = __half22float2(*(__half2*)&raw.z);
        float2 a3 = __half22float2(*(__half2*)&raw.w);
        float4 o0, o1;
        o0.x = a0.x * r * c0.x;  o0.y = a0.y * r * c0.y;
        o0.z = a1.x * r * c0.z;  o0.w = a1.y * r * c0.w;
        o1.x = a2.x * r * c1.x;  o1.y = a2.y * r * c1.y;
        o1.z = a3.x * r * c1.z;  o1.w = a3.y * r * c1.w;
        op[2 * g] = o0;
        op[2 * g + 1] = o1;
    }
}

// ---------------------------------------------------------------------------
extern "C" void kernel_launch(void* const* d_in, const int* in_sizes, int n_in,
                              void* d_out, int out_size) {
    const float* s     = (const float*)d_in[0];
    const int*   nrows = (const int*)d_in[1];
    const int*   ncols = (const int*)d_in[2];
    float*       out   = (float*)d_out;

    dim3 stGrid(SSPLIT, BB),   blk(256);
    dim3 fuGrid(RSPLIT, BB);
    dim3 rcGrid(MM / 256, BB);
    dim3 rsGrid(NN / 8, BB);

    // compacted layout offsets (device-side, deterministic)
    compute_offsets<<<1, 32>>>(nrows, ncols);

    // iter 0 (col): stage compacted + colsum (r = 1) -> partials in A
    stage_colsum0<<<stGrid, blk>>>(s, nrows, ncols);

    // iters 1..8: fused (c-from-partials prologue + row-norm + next colsum)
    rowcol_fused<SSPLIT, true ><<<fuGrid, blk>>>(nrows, ncols);  // A -> B
    rowcol_fused<RSPLIT, false><<<fuGrid, blk>>>(nrows, ncols);  // B -> A
    rowcol_fused<RSPLIT, true ><<<fuGrid, blk>>>(nrows, ncols);  // A -> B
    rowcol_fused<RSPLIT, false><<<fuGrid, blk>>>(nrows, ncols);  // B -> A

    // final c from A, then iter 9 (row) fused with output materialization
    reduce_c_final<<<rcGrid, blk>>>(ncols);
    rowsum_final_h<<<rsGrid, blk>>>(nrows, ncols, out);
}